// round 1
// baseline (speedup 1.0000x reference)
#include <cuda_runtime.h>
#include <cstdint>
#include <cstddef>

// Problem constants (fixed shapes for this problem)
#define G_   128
#define M_   512
#define D_   512
#define MA   513          // M+1 (augmented)
#define LD   520          // padded leading dim for E rows (multiple of 8 -> float4-friendly)
#define NORM_C (1.0f/1024.0f)

// ---------------- scratch (device globals: allocation-free) ----------------
__device__ float g_E[(size_t)G_ * MA * LD];   // exp(-c/lambda), ~137 MB
__device__ float g_u[G_ * LD];
__device__ float g_v[G_ * LD];
__device__ float g_invT[G_ * M_];             // 1/||tra_row||
__device__ float g_invD[G_ * M_];             // 1/||det_row||

// ---------------- norms ----------------
__global__ void norm_kernel(const float* __restrict__ x, int which) {
    float* out = which ? g_invD : g_invT;
    int warp = threadIdx.x >> 5, lane = threadIdx.x & 31;
    int row = blockIdx.x * 8 + warp;
    if (row >= G_ * M_) return;
    const float4* p = reinterpret_cast<const float4*>(x + (size_t)row * D_);
    float s = 0.f;
#pragma unroll
    for (int k = 0; k < 4; ++k) {
        float4 v = p[lane + k * 32];
        s += v.x * v.x + v.y * v.y + v.z * v.z + v.w * v.w;
    }
#pragma unroll
    for (int o = 16; o > 0; o >>= 1) s += __shfl_down_sync(0xffffffffu, s, o);
    if (lane == 0) out[row] = rsqrtf(s);
}

// ---------------- GEMM (tf32 mma.sync) + exp epilogue -> E core ----------------
#define BM 128
#define BN 128
#define BK 16
#define PADK 20   // (4*grp + tig) % 32 distinct -> conflict-free fragment loads

__device__ __forceinline__ uint32_t f2tf32(float x) {
    uint32_t r; asm("cvt.rna.tf32.f32 %0, %1;" : "=r"(r) : "f"(x)); return r;
}
__device__ __forceinline__ void cp16(void* s, const void* g) {
    uint32_t sa = (uint32_t)__cvta_generic_to_shared(s);
    asm volatile("cp.async.cg.shared.global [%0], [%1], 16;" :: "r"(sa), "l"(g));
}

__global__ void __launch_bounds__(256) gemm_exp_kernel(
    const float* __restrict__ det, const float* __restrict__ tra,
    const float* __restrict__ alpha, const float* __restrict__ eps)
{
    __shared__ float As[2][BM][PADK];   // tra tile  [m][k]
    __shared__ float Bs[2][BN][PADK];   // det tile  [n][k]
    const int g  = blockIdx.z;
    const int m0 = blockIdx.y * BM, n0 = blockIdx.x * BN;
    const float* Ag = tra + (size_t)(g * M_ + m0) * D_;
    const float* Bg = det + (size_t)(g * M_ + n0) * D_;
    const int tid  = threadIdx.x;
    const int lc4  = tid & 3, lrow = tid >> 2;   // global->smem load mapping
    const int lane = tid & 31, warp = tid >> 5;
    const int wm = warp >> 2, wn = warp & 3;     // 2 x 4 warp grid, warp tile 64x32
    const int grp = lane >> 2, tig = lane & 3;

    float acc[4][4][4];
#pragma unroll
    for (int a = 0; a < 4; ++a)
#pragma unroll
        for (int b = 0; b < 4; ++b)
#pragma unroll
            for (int c = 0; c < 4; ++c) acc[a][b][c] = 0.f;

    auto issue = [&](int kt, int buf) {
        const float* a = Ag + kt * BK;
        const float* b = Bg + kt * BK;
#pragma unroll
        for (int rr = 0; rr < 2; ++rr) {
            int row = lrow + rr * 64;
            cp16(&As[buf][row][lc4 * 4], a + (size_t)row * D_ + lc4 * 4);
            cp16(&Bs[buf][row][lc4 * 4], b + (size_t)row * D_ + lc4 * 4);
        }
    };

    issue(0, 0);
    asm volatile("cp.async.commit_group;");

    const int NKT = D_ / BK;   // 32 stages
    for (int kt = 0; kt < NKT; ++kt) {
        asm volatile("cp.async.wait_group 0;");
        __syncthreads();
        if (kt + 1 < NKT) { issue(kt + 1, (kt + 1) & 1); asm volatile("cp.async.commit_group;"); }
        const int buf = kt & 1;
#pragma unroll
        for (int ks = 0; ks < BK / 8; ++ks) {
            const int kb = ks * 8;
            uint32_t af[4][4], bf[4][2];
#pragma unroll
            for (int mt = 0; mt < 4; ++mt) {
                int row = wm * 64 + mt * 16 + grp;
                af[mt][0] = f2tf32(As[buf][row][kb + tig]);
                af[mt][1] = f2tf32(As[buf][row + 8][kb + tig]);
                af[mt][2] = f2tf32(As[buf][row][kb + tig + 4]);
                af[mt][3] = f2tf32(As[buf][row + 8][kb + tig + 4]);
            }
#pragma unroll
            for (int nt = 0; nt < 4; ++nt) {
                int rn = wn * 32 + nt * 8 + grp;
                bf[nt][0] = f2tf32(Bs[buf][rn][kb + tig]);
                bf[nt][1] = f2tf32(Bs[buf][rn][kb + tig + 4]);
            }
#pragma unroll
            for (int mt = 0; mt < 4; ++mt)
#pragma unroll
                for (int nt = 0; nt < 4; ++nt)
                    asm volatile(
                        "mma.sync.aligned.m16n8k8.row.col.f32.tf32.tf32.f32 "
                        "{%0,%1,%2,%3}, {%4,%5,%6,%7}, {%8,%9}, {%0,%1,%2,%3};"
                        : "+f"(acc[mt][nt][0]), "+f"(acc[mt][nt][1]),
                          "+f"(acc[mt][nt][2]), "+f"(acc[mt][nt][3])
                        : "r"(af[mt][0]), "r"(af[mt][1]), "r"(af[mt][2]), "r"(af[mt][3]),
                          "r"(bf[nt][0]), "r"(bf[nt][1]));
        }
    }

    // epilogue: affinity -> E = exp(-affinity/lambda)
    const float invL = 1.0f / (__expf(eps[0]) + 0.03f);
    float* Eg = g_E + (size_t)g * MA * LD;
    const float* iT = g_invT + g * M_;
    const float* iD = g_invD + g * M_;
#pragma unroll
    for (int mt = 0; mt < 4; ++mt) {
        int m = m0 + wm * 64 + mt * 16 + grp;
        float n1a = iT[m], n1b = iT[m + 8];
#pragma unroll
        for (int nt = 0; nt < 4; ++nt) {
            int n = n0 + wn * 32 + nt * 8 + 2 * tig;
            float n2a = iD[n], n2b = iD[n + 1];
            float2 r0, r1;
            r0.x = __expf(-acc[mt][nt][0] * n1a * n2a * invL);
            r0.y = __expf(-acc[mt][nt][1] * n1a * n2b * invL);
            r1.x = __expf(-acc[mt][nt][2] * n1b * n2a * invL);
            r1.y = __expf(-acc[mt][nt][3] * n1b * n2b * invL);
            *reinterpret_cast<float2*>(&Eg[(size_t)m * LD + n])       = r0;
            *reinterpret_cast<float2*>(&Eg[(size_t)(m + 8) * LD + n]) = r1;
        }
    }
}

// ---------------- bins (last row/col of E) + u init ----------------
__global__ void fill_kernel(const float* __restrict__ alpha, const float* __restrict__ eps) {
    int g = blockIdx.x, tid = threadIdx.x;
    float invL = 1.0f / (__expf(eps[0]) + 0.03f);
    float c = __expf(-alpha[0] * invL);
    float* Eg = g_E + (size_t)g * MA * LD;
    if (tid < MA) {
        Eg[(size_t)512 * LD + tid] = c;   // bin row (incl. corner)
        g_u[g * LD + tid] = 1.0f;
    }
    if (tid < 512) Eg[(size_t)tid * LD + 512] = c;  // bin col
}

// ---------------- Sinkhorn column pass: v = b / (E^T u) ----------------
__global__ void __launch_bounds__(544) col_kernel() {
    __shared__ float su[MA];
    int g = blockIdx.x, tid = threadIdx.x;
    for (int t = tid; t < MA; t += 544) su[t] = g_u[g * LD + t];
    __syncthreads();
    if (tid >= MA) return;
    const float* p = g_E + (size_t)g * MA * LD + tid;
    float a0 = 0.f, a1 = 0.f, a2 = 0.f, a3 = 0.f;
    int i = 0;
    for (; i + 8 <= MA; i += 8) {
        a0 += p[(i + 0) * LD] * su[i + 0];
        a1 += p[(i + 1) * LD] * su[i + 1];
        a2 += p[(i + 2) * LD] * su[i + 2];
        a3 += p[(i + 3) * LD] * su[i + 3];
        a0 += p[(i + 4) * LD] * su[i + 4];
        a1 += p[(i + 5) * LD] * su[i + 5];
        a2 += p[(i + 6) * LD] * su[i + 6];
        a3 += p[(i + 7) * LD] * su[i + 7];
    }
    for (; i < MA; ++i) a0 += p[i * LD] * su[i];
    float t = (a0 + a1) + (a2 + a3);
    float b = (tid == 512) ? (NORM_C * 512.0f) : NORM_C;
    g_v[g * LD + tid] = b / t;
}

// ---------------- Sinkhorn row pass: u = a / (E v) ----------------
__global__ void __launch_bounds__(256) row_kernel() {
    __shared__ float sv[MA];
    int g = blockIdx.y, tid = threadIdx.x;
    for (int t = tid; t < MA; t += 256) sv[t] = g_v[g * LD + t];
    __syncthreads();
    int i = blockIdx.x * 8 + (tid >> 5);
    if (i >= MA) return;
    int lane = tid & 31;
    const float* row = g_E + ((size_t)g * MA + i) * LD;
    float acc = 0.f;
#pragma unroll
    for (int k = 0; k < 16; ++k) acc += row[lane + k * 32] * sv[lane + k * 32];
    if (lane == 0) acc += row[512] * sv[512];
#pragma unroll
    for (int o = 16; o > 0; o >>= 1) acc += __shfl_down_sync(0xffffffffu, acc, o);
    if (lane == 0) {
        float a = (i == 512) ? (NORM_C * 512.0f) : NORM_C;
        g_u[g * LD + i] = a / acc;
    }
}

// ---------------- final: p = u_i * E_ij * v_j ----------------
__global__ void final_kernel(float* __restrict__ out) {
    int g = blockIdx.y, i = blockIdx.x, tid = threadIdx.x;
    float ui = g_u[g * LD + i];
    const float* row = g_E + ((size_t)g * MA + i) * LD;
    const float* v = g_v + g * LD;
    float* o = out + ((size_t)g * MA + i) * MA;
    for (int j = tid; j < MA; j += 128)
        o[j] = ui * row[j] * v[j];
}

// ---------------- launch ----------------
extern "C" void kernel_launch(void* const* d_in, const int* in_sizes, int n_in,
                              void* d_out, int out_size) {
    const float* det   = (const float*)d_in[0];
    const float* tra   = (const float*)d_in[1];
    const float* alpha = (const float*)d_in[2];
    const float* eps   = (const float*)d_in[3];
    float* out = (float*)d_out;

    norm_kernel<<<(G_ * M_) / 8, 256>>>(tra, 0);
    norm_kernel<<<(G_ * M_) / 8, 256>>>(det, 1);
    gemm_exp_kernel<<<dim3(M_ / BN, M_ / BM, G_), 256>>>(det, tra, alpha, eps);
    fill_kernel<<<G_, 544>>>(alpha, eps);
    for (int it = 0; it < 8; ++it) {
        col_kernel<<<G_, 544>>>();
        row_kernel<<<dim3(65, G_), 256>>>();
    }
    final_kernel<<<dim3(MA, G_), 128>>>(out);
}

// round 2
// speedup vs baseline: 1.1802x; 1.1802x over previous
#include <cuda_runtime.h>
#include <cuda_fp16.h>
#include <cstdint>
#include <cstddef>

#define G_   128
#define M_   512
#define D_   512
#define MA   513
#define LD   520          // padded leading dim (halves) -> 8B-aligned rows
#define NORM_C (1.0f/1024.0f)

// ---------------- scratch ----------------
__device__ __half g_E[(size_t)G_ * MA * LD];   // exp(-c/lambda), ~68 MB -> L2-resident
__device__ float g_invT[G_ * M_];
__device__ float g_invD[G_ * M_];

// ---------------- norms ----------------
__global__ void norm_kernel(const float* __restrict__ x, int which) {
    float* out = which ? g_invD : g_invT;
    int warp = threadIdx.x >> 5, lane = threadIdx.x & 31;
    int row = blockIdx.x * 8 + warp;
    if (row >= G_ * M_) return;
    const float4* p = reinterpret_cast<const float4*>(x + (size_t)row * D_);
    float s = 0.f;
#pragma unroll
    for (int k = 0; k < 4; ++k) {
        float4 v = p[lane + k * 32];
        s += v.x * v.x + v.y * v.y + v.z * v.z + v.w * v.w;
    }
#pragma unroll
    for (int o = 16; o > 0; o >>= 1) s += __shfl_down_sync(0xffffffffu, s, o);
    if (lane == 0) out[row] = rsqrtf(s);
}

// ---------------- GEMM (fp16 mma m16n8k16, fp32 accum) + exp epilogue ----------------
#define BM 128
#define BN 128
#define BK 16
#define PADK 20

__device__ __forceinline__ uint32_t pack_h2(float lo, float hi) {
    uint32_t r; asm("cvt.rn.f16x2.f32 %0, %1, %2;" : "=r"(r) : "f"(hi), "f"(lo)); return r;
}
__device__ __forceinline__ uint32_t ld_h2(const float* p) {
    float2 v = *reinterpret_cast<const float2*>(p);
    return pack_h2(v.x, v.y);
}
__device__ __forceinline__ void cp16(void* s, const void* g) {
    uint32_t sa = (uint32_t)__cvta_generic_to_shared(s);
    asm volatile("cp.async.cg.shared.global [%0], [%1], 16;" :: "r"(sa), "l"(g));
}

__global__ void __launch_bounds__(256) gemm_exp_kernel(
    const float* __restrict__ det, const float* __restrict__ tra,
    const float* __restrict__ eps)
{
    __shared__ float As[2][BM][PADK];
    __shared__ float Bs[2][BN][PADK];
    const int g  = blockIdx.z;
    const int m0 = blockIdx.y * BM, n0 = blockIdx.x * BN;
    const float* Ag = tra + (size_t)(g * M_ + m0) * D_;
    const float* Bg = det + (size_t)(g * M_ + n0) * D_;
    const int tid  = threadIdx.x;
    const int lc4  = tid & 3, lrow = tid >> 2;
    const int lane = tid & 31, warp = tid >> 5;
    const int wm = warp >> 2, wn = warp & 3;     // 2x4 warps, warp tile 64x32
    const int grp = lane >> 2, tig = lane & 3;

    float acc[4][4][4];
#pragma unroll
    for (int a = 0; a < 4; ++a)
#pragma unroll
        for (int b = 0; b < 4; ++b)
#pragma unroll
            for (int c = 0; c < 4; ++c) acc[a][b][c] = 0.f;

    auto issue = [&](int kt, int buf) {
        const float* a = Ag + kt * BK;
        const float* b = Bg + kt * BK;
#pragma unroll
        for (int rr = 0; rr < 2; ++rr) {
            int row = lrow + rr * 64;
            cp16(&As[buf][row][lc4 * 4], a + (size_t)row * D_ + lc4 * 4);
            cp16(&Bs[buf][row][lc4 * 4], b + (size_t)row * D_ + lc4 * 4);
        }
    };

    issue(0, 0);
    asm volatile("cp.async.commit_group;");

    const int NKT = D_ / BK;   // 32
    for (int kt = 0; kt < NKT; ++kt) {
        asm volatile("cp.async.wait_group 0;");
        __syncthreads();
        if (kt + 1 < NKT) { issue(kt + 1, (kt + 1) & 1); asm volatile("cp.async.commit_group;"); }
        const int buf = kt & 1;

        uint32_t af[4][4], bf[4][2];
#pragma unroll
        for (int mt = 0; mt < 4; ++mt) {
            int row = wm * 64 + mt * 16 + grp;
            af[mt][0] = ld_h2(&As[buf][row][2 * tig]);
            af[mt][1] = ld_h2(&As[buf][row + 8][2 * tig]);
            af[mt][2] = ld_h2(&As[buf][row][2 * tig + 8]);
            af[mt][3] = ld_h2(&As[buf][row + 8][2 * tig + 8]);
        }
#pragma unroll
        for (int nt = 0; nt < 4; ++nt) {
            int rn = wn * 32 + nt * 8 + grp;
            bf[nt][0] = ld_h2(&Bs[buf][rn][2 * tig]);
            bf[nt][1] = ld_h2(&Bs[buf][rn][2 * tig + 8]);
        }
#pragma unroll
        for (int mt = 0; mt < 4; ++mt)
#pragma unroll
            for (int nt = 0; nt < 4; ++nt)
                asm volatile(
                    "mma.sync.aligned.m16n8k16.row.col.f32.f16.f16.f32 "
                    "{%0,%1,%2,%3}, {%4,%5,%6,%7}, {%8,%9}, {%0,%1,%2,%3};"
                    : "+f"(acc[mt][nt][0]), "+f"(acc[mt][nt][1]),
                      "+f"(acc[mt][nt][2]), "+f"(acc[mt][nt][3])
                    : "r"(af[mt][0]), "r"(af[mt][1]), "r"(af[mt][2]), "r"(af[mt][3]),
                      "r"(bf[nt][0]), "r"(bf[nt][1]));
    }

    // epilogue: E = exp(-affinity/lambda) -> fp16
    const float invL = 1.0f / (__expf(eps[0]) + 0.03f);
    __half* Eg = g_E + (size_t)g * MA * LD;
    const float* iT = g_invT + g * M_;
    const float* iD = g_invD + g * M_;
#pragma unroll
    for (int mt = 0; mt < 4; ++mt) {
        int m = m0 + wm * 64 + mt * 16 + grp;
        float n1a = iT[m], n1b = iT[m + 8];
#pragma unroll
        for (int nt = 0; nt < 4; ++nt) {
            int n = n0 + wn * 32 + nt * 8 + 2 * tig;
            float n2a = iD[n], n2b = iD[n + 1];
            __half2 r0 = __floats2half2_rn(__expf(-acc[mt][nt][0] * n1a * n2a * invL),
                                           __expf(-acc[mt][nt][1] * n1a * n2b * invL));
            __half2 r1 = __floats2half2_rn(__expf(-acc[mt][nt][2] * n1b * n2a * invL),
                                           __expf(-acc[mt][nt][3] * n1b * n2b * invL));
            *reinterpret_cast<__half2*>(&Eg[(size_t)m * LD + n])       = r0;
            *reinterpret_cast<__half2*>(&Eg[(size_t)(m + 8) * LD + n]) = r1;
        }
    }
}

// ---------------- bins + zero pads ----------------
__global__ void fill_kernel(const float* __restrict__ alpha, const float* __restrict__ eps) {
    int g = blockIdx.x, tid = threadIdx.x;
    float invL = 1.0f / (__expf(eps[0]) + 0.03f);
    __half c = __float2half(__expf(-alpha[0] * invL));
    __half z = __float2half(0.f);
    __half* Eg = g_E + (size_t)g * MA * LD;
    // cols 512..519 for every row: col 512 = c (bin col / corner), 513..519 = 0
    for (int idx = tid; idx < MA * 8; idx += blockDim.x) {
        int row = idx >> 3, p = idx & 7;
        Eg[(size_t)row * LD + 512 + p] = (p == 0) ? c : z;
    }
    // bin row 512, cols 0..511
    for (int j = tid; j < 512; j += blockDim.x)
        Eg[(size_t)512 * LD + j] = c;
}

// ---------------- fused Sinkhorn (8 iters) + final output, one block per graph ----------------
__global__ void __launch_bounds__(512) sinkhorn_kernel(float* __restrict__ out) {
    __shared__ float su[520];
    __shared__ float sv[520];
    __shared__ float4 sred[4][132];
    const int g = blockIdx.x, tid = threadIdx.x;
    const __half* Eg = g_E + (size_t)g * MA * LD;
    const int q = tid & 127, r = tid >> 7;       // col-pass mapping
    const int w = tid >> 5, lane = tid & 31;     // row-pass mapping

    for (int t = tid; t < 520; t += 512) { su[t] = 1.f; sv[t] = 0.f; }
    __syncthreads();

    for (int it = 0; it < 8; ++it) {
        // ---- column pass: v = b / (E^T u) ----
        for (int quad = q; quad < 129; quad += 128) {
            const __half* base = Eg + 4 * quad;
            float4 acc = make_float4(0.f, 0.f, 0.f, 0.f);
            for (int i = r; i < MA; i += 4) {
                uint2 d = *reinterpret_cast<const uint2*>(base + (size_t)i * LD);
                float2 e01 = __half22float2(*reinterpret_cast<__half2*>(&d.x));
                float2 e23 = __half22float2(*reinterpret_cast<__half2*>(&d.y));
                float ui = su[i];
                acc.x += e01.x * ui; acc.y += e01.y * ui;
                acc.z += e23.x * ui; acc.w += e23.y * ui;
            }
            sred[r][quad] = acc;
        }
        __syncthreads();
        if (tid < 129) {
            float4 s0 = sred[0][tid], s1 = sred[1][tid], s2 = sred[2][tid], s3 = sred[3][tid];
            float s[4] = { s0.x + s1.x + s2.x + s3.x, s0.y + s1.y + s2.y + s3.y,
                           s0.z + s1.z + s2.z + s3.z, s0.w + s1.w + s2.w + s3.w };
            int c0 = 4 * tid;
#pragma unroll
            for (int j = 0; j < 4; ++j) {
                int c = c0 + j;
                if (c < MA) {
                    float b = (c == 512) ? (NORM_C * 512.0f) : NORM_C;
                    sv[c] = b / s[j];
                } else if (c < 520) sv[c] = 0.f;
            }
        }
        __syncthreads();
        // ---- row pass: u = a / (E v) ----
        for (int i = w; i < MA; i += 16) {
            const __half* row = Eg + (size_t)i * LD;
            float acc = 0.f;
#pragma unroll
            for (int k = 0; k < 4; ++k) {
                int j = 4 * lane + 128 * k;
                uint2 d = *reinterpret_cast<const uint2*>(row + j);
                float2 e01 = __half22float2(*reinterpret_cast<__half2*>(&d.x));
                float2 e23 = __half22float2(*reinterpret_cast<__half2*>(&d.y));
                acc += e01.x * sv[j] + e01.y * sv[j + 1] + e23.x * sv[j + 2] + e23.y * sv[j + 3];
            }
            if (lane == 0) acc += __half2float(row[512]) * sv[512];
#pragma unroll
            for (int o = 16; o > 0; o >>= 1) acc += __shfl_down_sync(0xffffffffu, acc, o);
            if (lane == 0) {
                float a = (i == 512) ? (NORM_C * 512.0f) : NORM_C;
                su[i] = a / acc;
            }
        }
        __syncthreads();
    }

    // ---- final: p = u_i * E_ij * v_j ----
    for (int i = w; i < MA; i += 16) {
        float ui = su[i];
        const __half* row = Eg + (size_t)i * LD;
        float* o = out + ((size_t)g * MA + i) * MA;
        for (int j = lane; j < MA; j += 32)
            o[j] = ui * __half2float(row[j]) * sv[j];
    }
}

// ---------------- launch ----------------
extern "C" void kernel_launch(void* const* d_in, const int* in_sizes, int n_in,
                              void* d_out, int out_size) {
    const float* det   = (const float*)d_in[0];
    const float* tra   = (const float*)d_in[1];
    const float* alpha = (const float*)d_in[2];
    const float* eps   = (const float*)d_in[3];
    float* out = (float*)d_out;

    norm_kernel<<<(G_ * M_) / 8, 256>>>(tra, 0);
    norm_kernel<<<(G_ * M_) / 8, 256>>>(det, 1);
    gemm_exp_kernel<<<dim3(M_ / BN, M_ / BM, G_), 256>>>(det, tra, eps);
    fill_kernel<<<G_, 512>>>(alpha, eps);
    sinkhorn_kernel<<<G_, 512>>>(out);
}

// round 4
// speedup vs baseline: 1.4883x; 1.2610x over previous
#include <cuda_runtime.h>
#include <cuda_fp16.h>
#include <cstdint>
#include <cstddef>

#define G_   128
#define M_   512
#define D_   512
#define MA   513
#define LD   520          // padded leading dim (halves)
#define NORM_C (1.0f/1024.0f)

// ---------------- scratch ----------------
__device__ __align__(16) __half g_E[(size_t)G_ * MA * LD];    // exp(-c/lambda), ~68 MB
__device__ __align__(16) __half g_Ah[(size_t)G_ * M_ * D_];   // normalized tra fp16
__device__ __align__(16) __half g_Bh[(size_t)G_ * M_ * D_];   // normalized det fp16

// ---------------- helpers ----------------
__device__ __forceinline__ uint32_t pack_h2(float lo, float hi) {
    uint32_t r; asm("cvt.rn.f16x2.f32 %0, %1, %2;" : "=r"(r) : "f"(hi), "f"(lo)); return r;
}
__device__ __forceinline__ uint32_t s2u(const void* p) {
    return (uint32_t)__cvta_generic_to_shared(p);
}
__device__ __forceinline__ void cp16(uint32_t saddr, const void* g) {
    asm volatile("cp.async.cg.shared.global [%0], [%1], 16;" :: "r"(saddr), "l"(g));
}
__device__ __forceinline__ void ldsm4(uint32_t* r, uint32_t a) {
    asm volatile("ldmatrix.sync.aligned.m8n8.x4.shared.b16 {%0,%1,%2,%3}, [%4];"
                 : "=r"(r[0]), "=r"(r[1]), "=r"(r[2]), "=r"(r[3]) : "r"(a));
}

// ---------------- normalize + fp16 convert (both inputs, one kernel) ----------------
__global__ void __launch_bounds__(256) normalize_kernel(const float* __restrict__ tra,
                                                        const float* __restrict__ det) {
    const float* x = blockIdx.y ? det : tra;
    __half* out = blockIdx.y ? g_Bh : g_Ah;
    int warp = threadIdx.x >> 5, lane = threadIdx.x & 31;
    int row = blockIdx.x * 8 + warp;
    const float4* p = reinterpret_cast<const float4*>(x + (size_t)row * D_);
    float4 v[4];
    float s = 0.f;
#pragma unroll
    for (int k = 0; k < 4; ++k) {
        v[k] = p[lane + k * 32];
        s += v[k].x * v[k].x + v[k].y * v[k].y + v[k].z * v[k].z + v[k].w * v[k].w;
    }
#pragma unroll
    for (int o = 16; o > 0; o >>= 1) s += __shfl_xor_sync(0xffffffffu, s, o);
    float inv = rsqrtf(s);
    uint2* po = reinterpret_cast<uint2*>(out + (size_t)row * D_);
#pragma unroll
    for (int k = 0; k < 4; ++k) {
        uint2 h;
        h.x = pack_h2(v[k].x * inv, v[k].y * inv);
        h.y = pack_h2(v[k].z * inv, v[k].w * inv);
        po[lane + k * 32] = h;
    }
}

// ---------------- fp16 GEMM (ldmatrix + mma.sync m16n8k16) + exp epilogue ----------------
#define BK 32          // halves per K-chunk
#define ROWH 40        // padded halves per smem row (80 B -> ldmatrix conflict-free)
#define TILE_H (128 * ROWH)

__global__ void __launch_bounds__(256) gemm_kernel(const float* __restrict__ eps) {
    __shared__ __half sA[2][TILE_H];
    __shared__ __half sB[2][TILE_H];
    const int tid = threadIdx.x;
    const int lane = tid & 31, warp = tid >> 5;
    const int wm = warp >> 2, wn = warp & 3;     // 2x4 warps, warp tile 64x32
    const int grp = lane >> 2, tig = lane & 3;
    const int g = blockIdx.z;
    const int m0 = blockIdx.y * 128, n0 = blockIdx.x * 128;
    const __half* gA = g_Ah + (size_t)(g * M_ + m0) * D_;
    const __half* gB = g_Bh + (size_t)(g * M_ + n0) * D_;
    const uint32_t sAu = s2u(sA), sBu = s2u(sB);

    // ldmatrix per-lane address components
    const int aRow = (((lane >> 3) & 1) << 3) + (lane & 7);  // + mt*16 + wm*64
    const int aCol = ((lane >> 4) << 3);                     // + ks*16
    const int bRow = ((lane >> 4) << 3) + (lane & 7);        // + p*16 + wn*32
    const int bCol = (((lane >> 3) & 1) << 3);

    float acc[4][4][4];
#pragma unroll
    for (int a = 0; a < 4; ++a)
#pragma unroll
        for (int b = 0; b < 4; ++b)
#pragma unroll
            for (int c = 0; c < 4; ++c) acc[a][b][c] = 0.f;

    const int lrow = tid >> 2, lc = tid & 3;   // 256 threads -> 2 chunks per tile half
    auto load = [&](int kc, int buf) {
        const __half* a = gA + kc * BK;
        const __half* b = gB + kc * BK;
#pragma unroll
        for (int t = 0; t < 2; ++t) {
            int row = lrow + t * 64;
            cp16(sAu + (buf * TILE_H + row * ROWH) * 2 + lc * 16, a + (size_t)row * D_ + lc * 8);
            cp16(sBu + (buf * TILE_H + row * ROWH) * 2 + lc * 16, b + (size_t)row * D_ + lc * 8);
        }
        asm volatile("cp.async.commit_group;" ::: "memory");
    };

    load(0, 0);
    const int NKT = D_ / BK;   // 16
    for (int kt = 0; kt < NKT; ++kt) {
        asm volatile("cp.async.wait_group 0;" ::: "memory");
        __syncthreads();
        if (kt + 1 < NKT) load(kt + 1, (kt + 1) & 1);
        const int buf = kt & 1;
        const uint32_t ab = sAu + (buf * TILE_H) * 2;
        const uint32_t bb = sBu + (buf * TILE_H) * 2;
#pragma unroll
        for (int ks = 0; ks < 2; ++ks) {
            uint32_t af[4][4], bf[2][4];
#pragma unroll
            for (int mt = 0; mt < 4; ++mt)
                ldsm4(af[mt], ab + ((wm * 64 + mt * 16 + aRow) * ROWH + ks * 16 + aCol) * 2);
#pragma unroll
            for (int p = 0; p < 2; ++p)
                ldsm4(bf[p], bb + ((wn * 32 + p * 16 + bRow) * ROWH + ks * 16 + bCol) * 2);
#pragma unroll
            for (int mt = 0; mt < 4; ++mt)
#pragma unroll
                for (int nt = 0; nt < 4; ++nt)
                    asm volatile(
                        "mma.sync.aligned.m16n8k16.row.col.f32.f16.f16.f32 "
                        "{%0,%1,%2,%3}, {%4,%5,%6,%7}, {%8,%9}, {%0,%1,%2,%3};"
                        : "+f"(acc[mt][nt][0]), "+f"(acc[mt][nt][1]),
                          "+f"(acc[mt][nt][2]), "+f"(acc[mt][nt][3])
                        : "r"(af[mt][0]), "r"(af[mt][1]), "r"(af[mt][2]), "r"(af[mt][3]),
                          "r"(bf[nt >> 1][(nt & 1) * 2]), "r"(bf[nt >> 1][(nt & 1) * 2 + 1]));
        }
    }

    // epilogue: E = exp(-affinity/lambda) -> fp16
    const float invL = 1.0f / (__expf(eps[0]) + 0.03f);
    __half* Eg = g_E + (size_t)g * MA * LD;
#pragma unroll
    for (int mt = 0; mt < 4; ++mt) {
        int m = m0 + wm * 64 + mt * 16 + grp;
#pragma unroll
        for (int nt = 0; nt < 4; ++nt) {
            int n = n0 + wn * 32 + nt * 8 + 2 * tig;
            uint32_t r0 = pack_h2(__expf(-acc[mt][nt][0] * invL),
                                  __expf(-acc[mt][nt][1] * invL));
            uint32_t r1 = pack_h2(__expf(-acc[mt][nt][2] * invL),
                                  __expf(-acc[mt][nt][3] * invL));
            *reinterpret_cast<uint32_t*>(&Eg[(size_t)m * LD + n])       = r0;
            *reinterpret_cast<uint32_t*>(&Eg[(size_t)(m + 8) * LD + n]) = r1;
        }
    }
}

// ---------------- bins + zero pads ----------------
__global__ void fill_kernel(const float* __restrict__ alpha, const float* __restrict__ eps) {
    int g = blockIdx.x, tid = threadIdx.x;
    float invL = 1.0f / (__expf(eps[0]) + 0.03f);
    __half c = __float2half(__expf(-alpha[0] * invL));
    __half z = __float2half(0.f);
    __half* Eg = g_E + (size_t)g * MA * LD;
    for (int idx = tid; idx < MA * 8; idx += blockDim.x) {
        int row = idx >> 3, p = idx & 7;
        Eg[(size_t)row * LD + 512 + p] = (p == 0) ? c : z;
    }
    for (int j = tid; j < 512; j += blockDim.x)
        Eg[(size_t)512 * LD + j] = c;
}

// ---------------- fused Sinkhorn (8 iters) + final output ----------------
__global__ void __launch_bounds__(512) sinkhorn_kernel(float* __restrict__ out) {
    __shared__ float su[520];
    __shared__ float sv[520];
    __shared__ float4 sred[4][132];
    const int g = blockIdx.x, tid = threadIdx.x;
    const __half* Eg = g_E + (size_t)g * MA * LD;
    const int q = tid & 127, r = tid >> 7;
    const int w = tid >> 5, lane = tid & 31;

    for (int t = tid; t < 520; t += 512) { su[t] = 1.f; sv[t] = 0.f; }
    __syncthreads();

    for (int it = 0; it < 8; ++it) {
        // column pass: v = b / (E^T u)
        for (int quad = q; quad < 129; quad += 128) {
            const __half* base = Eg + 4 * quad;
            float4 acc = make_float4(0.f, 0.f, 0.f, 0.f);
            for (int i = r; i < MA; i += 4) {
                uint2 d = *reinterpret_cast<const uint2*>(base + (size_t)i * LD);
                float2 e01 = __half22float2(*reinterpret_cast<__half2*>(&d.x));
                float2 e23 = __half22float2(*reinterpret_cast<__half2*>(&d.y));
                float ui = su[i];
                acc.x += e01.x * ui; acc.y += e01.y * ui;
                acc.z += e23.x * ui; acc.w += e23.y * ui;
            }
            sred[r][quad] = acc;
        }
        __syncthreads();
        if (tid < 129) {
            float4 s0 = sred[0][tid], s1 = sred[1][tid], s2 = sred[2][tid], s3 = sred[3][tid];
            float s[4] = { s0.x + s1.x + s2.x + s3.x, s0.y + s1.y + s2.y + s3.y,
                           s0.z + s1.z + s2.z + s3.z, s0.w + s1.w + s2.w + s3.w };
            int c0 = 4 * tid;
#pragma unroll
            for (int j = 0; j < 4; ++j) {
                int c = c0 + j;
                if (c < MA) {
                    float b = (c == 512) ? (NORM_C * 512.0f) : NORM_C;
                    sv[c] = b / s[j];
                } else if (c < 520) sv[c] = 0.f;
            }
        }
        __syncthreads();
        // row pass: u = a / (E v)
        for (int i = w; i < MA; i += 16) {
            const __half* row = Eg + (size_t)i * LD;
            float acc = 0.f;
#pragma unroll
            for (int k = 0; k < 4; ++k) {
                int j = 4 * lane + 128 * k;
                uint2 d = *reinterpret_cast<const uint2*>(row + j);
                float2 e01 = __half22float2(*reinterpret_cast<__half2*>(&d.x));
                float2 e23 = __half22float2(*reinterpret_cast<__half2*>(&d.y));
                acc += e01.x * sv[j] + e01.y * sv[j + 1] + e23.x * sv[j + 2] + e23.y * sv[j + 3];
            }
            if (lane == 0) acc += __half2float(row[512]) * sv[512];
#pragma unroll
            for (int o = 16; o > 0; o >>= 1) acc += __shfl_down_sync(0xffffffffu, acc, o);
            if (lane == 0) {
                float a = (i == 512) ? (NORM_C * 512.0f) : NORM_C;
                su[i] = a / acc;
            }
        }
        __syncthreads();
    }

    // final: p = u_i * E_ij * v_j
    for (int i = w; i < MA; i += 16) {
        float ui = su[i];
        const __half* row = Eg + (size_t)i * LD;
        float* o = out + ((size_t)g * MA + i) * MA;
        for (int j = lane; j < MA; j += 32)
            o[j] = ui * __half2float(row[j]) * sv[j];
    }
}

// ---------------- launch ----------------
extern "C" void kernel_launch(void* const* d_in, const int* in_sizes, int n_in,
                              void* d_out, int out_size) {
    const float* det   = (const float*)d_in[0];
    const float* tra   = (const float*)d_in[1];
    const float* alpha = (const float*)d_in[2];
    const float* eps   = (const float*)d_in[3];
    float* out = (float*)d_out;

    normalize_kernel<<<dim3((G_ * M_) / 8, 2), 256>>>(tra, det);
    gemm_kernel<<<dim3(4, 4, G_), 256>>>(eps);
    fill_kernel<<<G_, 512>>>(alpha, eps);
    sinkhorn_kernel<<<G_, 512>>>(out);
}

// round 6
// speedup vs baseline: 1.8865x; 1.2676x over previous
#include <cuda_runtime.h>
#include <cuda_fp16.h>
#include <cstdint>
#include <cstddef>

#define G_   128
#define M_   512
#define D_   512
#define MA   513
#define LD2  512          // dense E leading dim (no bins stored)
#define NORM_C (1.0f/1024.0f)

// ---------------- scratch ----------------
__device__ __align__(16) __half g_E[(size_t)G_ * M_ * LD2];   // exp(-c/lambda), 64 MB
__device__ __align__(16) __half g_Ah[(size_t)G_ * M_ * D_];   // normalized tra fp16
__device__ __align__(16) __half g_Bh[(size_t)G_ * M_ * D_];   // normalized det fp16

// ---------------- helpers ----------------
__device__ __forceinline__ uint32_t pack_h2(float lo, float hi) {
    uint32_t r; asm("cvt.rn.f16x2.f32 %0, %1, %2;" : "=r"(r) : "f"(hi), "f"(lo)); return r;
}
__device__ __forceinline__ uint32_t s2u(const void* p) {
    return (uint32_t)__cvta_generic_to_shared(p);
}
__device__ __forceinline__ void cp16(uint32_t saddr, const void* g) {
    asm volatile("cp.async.cg.shared.global [%0], [%1], 16;" :: "r"(saddr), "l"(g));
}
__device__ __forceinline__ void ldsm4(uint32_t* r, uint32_t a) {
    asm volatile("ldmatrix.sync.aligned.m8n8.x4.shared.b16 {%0,%1,%2,%3}, [%4];"
                 : "=r"(r[0]), "=r"(r[1]), "=r"(r[2]), "=r"(r[3]) : "r"(a));
}
// load one E row slice (16 halves at cols lane*16..lane*16+15) as 8 float2
__device__ __forceinline__ void load_row(const __half* Eg, int i, int lane, float2* e) {
    const uint4* rp = reinterpret_cast<const uint4*>(Eg + (size_t)i * LD2) + lane * 2;
    uint4 d0 = rp[0], d1 = rp[1];
    e[0] = __half22float2(*reinterpret_cast<__half2*>(&d0.x));
    e[1] = __half22float2(*reinterpret_cast<__half2*>(&d0.y));
    e[2] = __half22float2(*reinterpret_cast<__half2*>(&d0.z));
    e[3] = __half22float2(*reinterpret_cast<__half2*>(&d0.w));
    e[4] = __half22float2(*reinterpret_cast<__half2*>(&d1.x));
    e[5] = __half22float2(*reinterpret_cast<__half2*>(&d1.y));
    e[6] = __half22float2(*reinterpret_cast<__half2*>(&d1.z));
    e[7] = __half22float2(*reinterpret_cast<__half2*>(&d1.w));
}

// ---------------- normalize + fp16 convert ----------------
__global__ void __launch_bounds__(256) normalize_kernel(const float* __restrict__ tra,
                                                        const float* __restrict__ det) {
    const float* x = blockIdx.y ? det : tra;
    __half* out = blockIdx.y ? g_Bh : g_Ah;
    int warp = threadIdx.x >> 5, lane = threadIdx.x & 31;
    int row = blockIdx.x * 8 + warp;
    const float4* p = reinterpret_cast<const float4*>(x + (size_t)row * D_);
    float4 v[4];
    float s = 0.f;
#pragma unroll
    for (int k = 0; k < 4; ++k) {
        v[k] = p[lane + k * 32];
        s += v[k].x * v[k].x + v[k].y * v[k].y + v[k].z * v[k].z + v[k].w * v[k].w;
    }
#pragma unroll
    for (int o = 16; o > 0; o >>= 1) s += __shfl_xor_sync(0xffffffffu, s, o);
    float inv = rsqrtf(s);
    uint2* po = reinterpret_cast<uint2*>(out + (size_t)row * D_);
#pragma unroll
    for (int k = 0; k < 4; ++k) {
        uint2 h;
        h.x = pack_h2(v[k].x * inv, v[k].y * inv);
        h.y = pack_h2(v[k].z * inv, v[k].w * inv);
        po[lane + k * 32] = h;
    }
}

// ---------------- fp16 GEMM (ldmatrix + mma.sync m16n8k16) + exp epilogue ----------------
#define BK 32
#define ROWH 40
#define TILE_H (128 * ROWH)

__global__ void __launch_bounds__(256) gemm_kernel(const float* __restrict__ eps) {
    __shared__ __half sA[2][TILE_H];
    __shared__ __half sB[2][TILE_H];
    const int tid = threadIdx.x;
    const int lane = tid & 31, warp = tid >> 5;
    const int wm = warp >> 2, wn = warp & 3;
    const int grp = lane >> 2, tig = lane & 3;
    const int g = blockIdx.z;
    const int m0 = blockIdx.y * 128, n0 = blockIdx.x * 128;
    const __half* gA = g_Ah + (size_t)(g * M_ + m0) * D_;
    const __half* gB = g_Bh + (size_t)(g * M_ + n0) * D_;
    const uint32_t sAu = s2u(sA), sBu = s2u(sB);

    const int aRow = (((lane >> 3) & 1) << 3) + (lane & 7);
    const int aCol = ((lane >> 4) << 3);
    const int bRow = ((lane >> 4) << 3) + (lane & 7);
    const int bCol = (((lane >> 3) & 1) << 3);

    float acc[4][4][4];
#pragma unroll
    for (int a = 0; a < 4; ++a)
#pragma unroll
        for (int b = 0; b < 4; ++b)
#pragma unroll
            for (int c = 0; c < 4; ++c) acc[a][b][c] = 0.f;

    const int lrow = tid >> 2, lc = tid & 3;
    auto load = [&](int kc, int buf) {
        const __half* a = gA + kc * BK;
        const __half* b = gB + kc * BK;
#pragma unroll
        for (int t = 0; t < 2; ++t) {
            int row = lrow + t * 64;
            cp16(sAu + (buf * TILE_H + row * ROWH) * 2 + lc * 16, a + (size_t)row * D_ + lc * 8);
            cp16(sBu + (buf * TILE_H + row * ROWH) * 2 + lc * 16, b + (size_t)row * D_ + lc * 8);
        }
        asm volatile("cp.async.commit_group;" ::: "memory");
    };

    load(0, 0);
    const int NKT = D_ / BK;
    for (int kt = 0; kt < NKT; ++kt) {
        asm volatile("cp.async.wait_group 0;" ::: "memory");
        __syncthreads();
        if (kt + 1 < NKT) load(kt + 1, (kt + 1) & 1);
        const int buf = kt & 1;
        const uint32_t ab = sAu + (buf * TILE_H) * 2;
        const uint32_t bb = sBu + (buf * TILE_H) * 2;
#pragma unroll
        for (int ks = 0; ks < 2; ++ks) {
            uint32_t af[4][4], bf[2][4];
#pragma unroll
            for (int mt = 0; mt < 4; ++mt)
                ldsm4(af[mt], ab + ((wm * 64 + mt * 16 + aRow) * ROWH + ks * 16 + aCol) * 2);
#pragma unroll
            for (int p = 0; p < 2; ++p)
                ldsm4(bf[p], bb + ((wn * 32 + p * 16 + bRow) * ROWH + ks * 16 + bCol) * 2);
#pragma unroll
            for (int mt = 0; mt < 4; ++mt)
#pragma unroll
                for (int nt = 0; nt < 4; ++nt)
                    asm volatile(
                        "mma.sync.aligned.m16n8k16.row.col.f32.f16.f16.f32 "
                        "{%0,%1,%2,%3}, {%4,%5,%6,%7}, {%8,%9}, {%0,%1,%2,%3};"
                        : "+f"(acc[mt][nt][0]), "+f"(acc[mt][nt][1]),
                          "+f"(acc[mt][nt][2]), "+f"(acc[mt][nt][3])
                        : "r"(af[mt][0]), "r"(af[mt][1]), "r"(af[mt][2]), "r"(af[mt][3]),
                          "r"(bf[nt >> 1][(nt & 1) * 2]), "r"(bf[nt >> 1][(nt & 1) * 2 + 1]));
        }
    }

    const float invL = 1.0f / (__expf(eps[0]) + 0.03f);
    __half* Eg = g_E + (size_t)g * M_ * LD2;
#pragma unroll
    for (int mt = 0; mt < 4; ++mt) {
        int m = m0 + wm * 64 + mt * 16 + grp;
#pragma unroll
        for (int nt = 0; nt < 4; ++nt) {
            int n = n0 + wn * 32 + nt * 8 + 2 * tig;
            uint32_t r0 = pack_h2(__expf(-acc[mt][nt][0] * invL),
                                  __expf(-acc[mt][nt][1] * invL));
            uint32_t r1 = pack_h2(__expf(-acc[mt][nt][2] * invL),
                                  __expf(-acc[mt][nt][3] * invL));
            *reinterpret_cast<uint32_t*>(&Eg[(size_t)m * LD2 + n])       = r0;
            *reinterpret_cast<uint32_t*>(&Eg[(size_t)(m + 8) * LD2 + n]) = r1;
        }
    }
}

// ---------------- fused Sinkhorn: 9 E-passes total, bins analytic ----------------
// smem: sv[520] | swsum[32] | sscal[8] | scol[32*512]
#define SH_SV    0
#define SH_WSUM  520
#define SH_SCAL  552
#define SH_COL   560
#define SH_FLOATS (560 + 32 * 512)

__global__ void __launch_bounds__(1024, 1) sinkhorn_kernel(
    float* __restrict__ out, const float* __restrict__ alpha, const float* __restrict__ eps)
{
    extern __shared__ float sh[];
    float* sv    = sh + SH_SV;
    float* swsum = sh + SH_WSUM;
    float* sscal = sh + SH_SCAL;
    float* scol  = sh + SH_COL;
    const int g = blockIdx.x, tid = threadIdx.x, w = tid >> 5, lane = tid & 31;
    const __half* Eg = g_E + (size_t)g * M_ * LD2;
    const float invL = 1.f / (__expf(eps[0]) + 0.03f);
    const float c = __expf(-alpha[0] * invL);
    const float AB512 = NORM_C * 512.f;      // a_aug[-1] == b_aug[-1]
    const int row0 = w * 16;
    float2 e[8];

    // ---- pass 0: column sums with u == 1 ----
    {
        float2 ca[8];
#pragma unroll
        for (int q = 0; q < 8; ++q) ca[q] = make_float2(0.f, 0.f);
#pragma unroll 4
        for (int t = 0; t < 16; ++t) {
            load_row(Eg, row0 + t, lane, e);
#pragma unroll
            for (int q = 0; q < 8; ++q) { ca[q].x += e[q].x; ca[q].y += e[q].y; }
        }
        float* dst = scol + w * 512 + lane * 16;
#pragma unroll
        for (int q = 0; q < 8; ++q) { dst[2 * q] = ca[q].x; dst[2 * q + 1] = ca[q].y; }
    }
    __syncthreads();
    if (tid < 512) {
        float s = c;                        // bin-row contribution, u512 = 1
#pragma unroll
        for (int ww = 0; ww < 32; ++ww) s += scol[ww * 512 + tid];
        sv[tid] = NORM_C / s;
    } else if (tid == 512) {
        sv[512] = AB512 / (c * 513.f);      // colsum_512 = c * sum(u) = c * 513
    }
    __syncthreads();
    if (w == 0) {                           // sumV -> u512
        float p = 0.f;
#pragma unroll
        for (int k = 0; k < 16; ++k) p += sv[lane + 32 * k];
#pragma unroll
        for (int o = 16; o > 0; o >>= 1) p += __shfl_xor_sync(0xffffffffu, p, o);
        if (lane == 0) sscal[0] = AB512 / (c * (p + sv[512]));
    }
    __syncthreads();

    // ---- 7 fused passes: (row update k) + (col accumulation for k+1) in one E read ----
    for (int it = 0; it < 7; ++it) {
        float2 vr[8];
#pragma unroll
        for (int q = 0; q < 8; ++q) vr[q] = *reinterpret_cast<float2*>(&sv[lane * 16 + 2 * q]);
        const float v512 = sv[512];
        const float u512 = sscal[0];
        float2 ca[8];
#pragma unroll
        for (int q = 0; q < 8; ++q) ca[q] = make_float2(0.f, 0.f);
        float wsum = 0.f;
#pragma unroll 2
        for (int t = 0; t < 16; ++t) {
            load_row(Eg, row0 + t, lane, e);
            float rs = 0.f;
#pragma unroll
            for (int q = 0; q < 8; ++q) rs += e[q].x * vr[q].x + e[q].y * vr[q].y;
#pragma unroll
            for (int o = 16; o > 0; o >>= 1) rs += __shfl_xor_sync(0xffffffffu, rs, o);
            float u = NORM_C / (rs + c * v512);
            wsum += u;
#pragma unroll
            for (int q = 0; q < 8; ++q) { ca[q].x += u * e[q].x; ca[q].y += u * e[q].y; }
        }
        {
            float* dst = scol + w * 512 + lane * 16;
#pragma unroll
            for (int q = 0; q < 8; ++q) { dst[2 * q] = ca[q].x; dst[2 * q + 1] = ca[q].y; }
        }
        if (lane == 0) swsum[w] = wsum;
        __syncthreads();
        if (tid < 512) {
            float s = c * u512;
#pragma unroll
            for (int ww = 0; ww < 32; ++ww) s += scol[ww * 512 + tid];
            sv[tid] = NORM_C / s;
        } else if (tid == 512) {
            float sU = u512;
#pragma unroll
            for (int ww = 0; ww < 32; ++ww) sU += swsum[ww];
            sv[512] = AB512 / (c * sU);
        }
        __syncthreads();
        if (w == 0) {
            float p = 0.f;
#pragma unroll
            for (int k = 0; k < 16; ++k) p += sv[lane + 32 * k];
#pragma unroll
            for (int o = 16; o > 0; o >>= 1) p += __shfl_xor_sync(0xffffffffu, p, o);
            if (lane == 0) sscal[0] = AB512 / (c * (p + sv[512]));
        }
        __syncthreads();
    }

    // ---- final pass: u_8 + output write in one E read ----
    {
        float2 vr[8];
#pragma unroll
        for (int q = 0; q < 8; ++q) vr[q] = *reinterpret_cast<float2*>(&sv[lane * 16 + 2 * q]);
        const float v512 = sv[512];
        const float u512 = sscal[0];
        float* og = out + (size_t)g * MA * MA;
#pragma unroll 2
        for (int t = 0; t < 16; ++t) {
            int i = row0 + t;
            load_row(Eg, i, lane, e);
            float rs = 0.f;
#pragma unroll
            for (int q = 0; q < 8; ++q) rs += e[q].x * vr[q].x + e[q].y * vr[q].y;
#pragma unroll
            for (int o = 16; o > 0; o >>= 1) rs += __shfl_xor_sync(0xffffffffu, rs, o);
            float u = NORM_C / (rs + c * v512);
            float* orow = og + (size_t)i * MA + lane * 16;
#pragma unroll
            for (int q = 0; q < 8; ++q) {
                orow[2 * q]     = u * e[q].x * vr[q].x;
                orow[2 * q + 1] = u * e[q].y * vr[q].y;
            }
            if (lane == 0) og[(size_t)i * MA + 512] = u * c * v512;
        }
        // bin row
        for (int j = tid; j < 512; j += 1024)
            og[(size_t)512 * MA + j] = u512 * c * sv[j];
        if (tid == 0) og[(size_t)512 * MA + 512] = u512 * c * v512;
    }
}

// ---------------- launch ----------------
extern "C" void kernel_launch(void* const* d_in, const int* in_sizes, int n_in,
                              void* d_out, int out_size) {
    const float* det   = (const float*)d_in[0];
    const float* tra   = (const float*)d_in[1];
    const float* alpha = (const float*)d_in[2];
    const float* eps   = (const float*)d_in[3];
    float* out = (float*)d_out;

    cudaFuncSetAttribute(sinkhorn_kernel, cudaFuncAttributeMaxDynamicSharedMemorySize,
                         SH_FLOATS * (int)sizeof(float));

    normalize_kernel<<<dim3((G_ * M_) / 8, 2), 256>>>(tra, det);
    gemm_kernel<<<dim3(4, 4, G_), 256>>>(eps);
    sinkhorn_kernel<<<G_, 1024, SH_FLOATS * sizeof(float)>>>(out, alpha, eps);
}